// round 3
// baseline (speedup 1.0000x reference)
#include <cuda_runtime.h>

#define BB 2048
#define TT 512
#define II 64
#define G  9   // 3 gates * H=3

// Scratch: xW0 precomputed, layout [T][G][B] for coalesced recurrence reads.
__device__ float g_xw0[(size_t)TT * G * BB];

__device__ __forceinline__ float sigm(float x) {
    // 1/(1+e^-x); MUFU.EX2 + MUFU.RCP path. Safe at extremes (inf -> 0/1).
    return __fdividef(1.0f, 1.0f + __expf(-x));
}

__device__ __forceinline__ float tanh_fast(float x) {
    // tanh(x) = (1 - e^-2x) / (1 + e^-2x); clamp to avoid inf/inf NaN for very negative x
    float xc = fmaxf(x, -20.0f);
    float e = __expf(-2.0f * xc);
    return __fdividef(1.0f - e, 1.0f + e);
}

// -------------------------------------------------------------------------
// Phase A: xw0[t][g][b] = b_ih0[g] + sum_i x[b][t][i] * W_ih0[g][i]
// One thread per (b, t). Lanes consecutive in b -> coalesced scratch writes.
// -------------------------------------------------------------------------
__global__ void __launch_bounds__(256) phaseA(
    const float* __restrict__ x,
    const float* __restrict__ W_ih0,
    const float* __restrict__ b_ih0)
{
    __shared__ float Ws[G * II];
    __shared__ float bs[G];
    for (int i = threadIdx.x; i < G * II; i += blockDim.x) Ws[i] = W_ih0[i];
    if (threadIdx.x < G) bs[threadIdx.x] = b_ih0[threadIdx.x];
    __syncthreads();

    int idx = blockIdx.x * blockDim.x + threadIdx.x;   // 0 .. B*T-1
    int b = idx & (BB - 1);
    int t = idx >> 11;                                  // / 2048

    const float4* xp = reinterpret_cast<const float4*>(x + ((size_t)b * TT + t) * II);
    const float4* wp = reinterpret_cast<const float4*>(Ws);

    float acc[G];
#pragma unroll
    for (int g = 0; g < G; g++) acc[g] = bs[g];

#pragma unroll
    for (int i = 0; i < II / 4; i++) {
        float4 xv = xp[i];
#pragma unroll
        for (int g = 0; g < G; g++) {
            float4 wv = wp[g * (II / 4) + i];
            acc[g] += xv.x * wv.x + xv.y * wv.y + xv.z * wv.z + xv.w * wv.w;
        }
    }

    float* o = g_xw0 + (size_t)t * G * BB + b;
#pragma unroll
    for (int g = 0; g < G; g++) o[(size_t)g * BB] = acc[g];
}

// -------------------------------------------------------------------------
// Phase B: fused two-layer recurrence, one thread per batch element.
// Layer 1 runs one step behind layer 0 so their latency chains overlap.
// -------------------------------------------------------------------------
__device__ __forceinline__ void l0_step(
    const float xw[G], const float whh[G][3], const float bh[G],
    const float h[3], float hn_out[3])
{
    float gh[G];
#pragma unroll
    for (int g = 0; g < G; g++)
        gh[g] = bh[g] + whh[g][0] * h[0] + whh[g][1] * h[1] + whh[g][2] * h[2];
#pragma unroll
    for (int j = 0; j < 3; j++) {
        float r = sigm(xw[j] + gh[j]);
        float z = sigm(xw[3 + j] + gh[3 + j]);
        float n = tanh_fast(xw[6 + j] + r * gh[6 + j]);
        hn_out[j] = n + z * (h[j] - n);
    }
}

__device__ __forceinline__ void l1_step(
    const float h0in[3],
    const float wih[G][3], const float bi[G],
    const float whh[G][3], const float bh[G],
    float h1[3])
{
    float xg[G], gh[G];
#pragma unroll
    for (int g = 0; g < G; g++) {
        xg[g] = bi[g] + wih[g][0] * h0in[0] + wih[g][1] * h0in[1] + wih[g][2] * h0in[2];
        gh[g] = bh[g] + whh[g][0] * h1[0]  + whh[g][1] * h1[1]  + whh[g][2] * h1[2];
    }
    float hn[3];
#pragma unroll
    for (int j = 0; j < 3; j++) {
        float r = sigm(xg[j] + gh[j]);
        float z = sigm(xg[3 + j] + gh[3 + j]);
        float n = tanh_fast(xg[6 + j] + r * gh[6 + j]);
        hn[j] = n + z * (h1[j] - n);
    }
#pragma unroll
    for (int j = 0; j < 3; j++) h1[j] = hn[j];
}

__global__ void __launch_bounds__(32, 1) gru_rec(
    const float* __restrict__ W_hh0, const float* __restrict__ b_hh0,
    const float* __restrict__ W_ih1, const float* __restrict__ b_ih1,
    const float* __restrict__ W_hh1, const float* __restrict__ b_hh1,
    float* __restrict__ out)
{
    int b = blockIdx.x * 32 + threadIdx.x;

    float whh0[G][3], wih1[G][3], whh1[G][3];
    float bh0[G], bi1[G], bh1[G];
#pragma unroll
    for (int g = 0; g < G; g++) {
        bh0[g] = __ldg(b_hh0 + g);
        bi1[g] = __ldg(b_ih1 + g);
        bh1[g] = __ldg(b_hh1 + g);
#pragma unroll
        for (int k = 0; k < 3; k++) {
            whh0[g][k] = __ldg(W_hh0 + g * 3 + k);
            wih1[g][k] = __ldg(W_ih1 + g * 3 + k);
            whh1[g][k] = __ldg(W_hh1 + g * 3 + k);
        }
    }

    float h0[3] = {0.f, 0.f, 0.f};
    float h1[3] = {0.f, 0.f, 0.f};

    const float* base = g_xw0 + b;

    // 2-deep prefetch of per-step gate inputs (covers L2 latency)
    float xc[G], xnx[G];
#pragma unroll
    for (int g = 0; g < G; g++) xc[g]  = base[(size_t)(0 * G + g) * BB];
#pragma unroll
    for (int g = 0; g < G; g++) xnx[g] = base[(size_t)(1 * G + g) * BB];

#pragma unroll 2
    for (int t = 0; t < TT; t++) {
        float xf[G];
        if (t + 2 < TT) {
            const float* pf = base + (size_t)(t + 2) * G * BB;
#pragma unroll
            for (int g = 0; g < G; g++) xf[g] = pf[(size_t)g * BB];
        } else {
#pragma unroll
            for (int g = 0; g < G; g++) xf[g] = 0.f;
        }

        // Layer-0 step t (reads h0 = h0_{t-1})
        float h0n[3];
        l0_step(xc, whh0, bh0, h0, h0n);

        // Layer-1 step t-1 (also reads h0 = h0_{t-1}) -- independent chain
        if (t > 0)
            l1_step(h0, wih1, bi1, whh1, bh1, h1);

#pragma unroll
        for (int j = 0; j < 3; j++) h0[j] = h0n[j];
#pragma unroll
        for (int g = 0; g < G; g++) { xc[g] = xnx[g]; xnx[g] = xf[g]; }
    }
    // Final layer-1 step (t = T-1)
    l1_step(h0, wih1, bi1, whh1, bh1, h1);

    out[b * 3 + 0] = h1[0];
    out[b * 3 + 1] = h1[1];
    out[b * 3 + 2] = h1[2];
}

extern "C" void kernel_launch(void* const* d_in, const int* in_sizes, int n_in,
                              void* d_out, int out_size)
{
    const float* x     = (const float*)d_in[0];
    const float* W_ih0 = (const float*)d_in[1];
    const float* W_hh0 = (const float*)d_in[2];
    const float* b_ih0 = (const float*)d_in[3];
    const float* b_hh0 = (const float*)d_in[4];
    const float* W_ih1 = (const float*)d_in[5];
    const float* W_hh1 = (const float*)d_in[6];
    const float* b_ih1 = (const float*)d_in[7];
    const float* b_hh1 = (const float*)d_in[8];
    float* out = (float*)d_out;

    phaseA<<<(BB * TT) / 256, 256>>>(x, W_ih0, b_ih0);
    gru_rec<<<BB / 32, 32>>>(W_hh0, b_hh0, W_ih1, b_ih1, W_hh1, b_hh1, out);
}